// round 12
// baseline (speedup 1.0000x reference)
#include <cuda_runtime.h>
#include <cuda_fp16.h>
#include <cstdint>

// Complex attention via portable mma.sync m16n8k16 fp16 (f32 accum).
// Round 12: Karatsuba 3-mult complex product on PV stage:
//   u1=Pr*Vr, u2=Pi*Vi, u3=(Pr+Pi)*(Vr+Vi); O_re=u1-u2, O_im=u3-u1-u2.
// Vs baked fp32->fp16 in prepass; Ps summed in fp32 in softmax. -12.5% MMAs.
#define SLEN 2048
#define PLANE (4*8*2048*64)
#define TEMP_INV 0.125f
#define NT 32
#define SGNH 0x80008000u

// smem uint4 units: K[2][1024] @0, V[2][1024] @2048, Vs[2][512] @4096,
// P[4 warps][384] @5120 (ppr 256 uint2, ppi 256, pps 256)
#define SMEM_BYTES (6656*16)   // 106496

__device__ uint4 gK[32*32*1024];
__device__ uint4 gV[32*32*1024];
__device__ uint2 gVs[32*32*1024];

static __device__ __forceinline__ void mma16(float* d, const uint32_t* a,
                                             uint32_t b0, uint32_t b1) {
    asm volatile("mma.sync.aligned.m16n8k16.row.col.f32.f16.f16.f32 "
                 "{%0,%1,%2,%3},{%4,%5,%6,%7},{%8,%9},{%0,%1,%2,%3};"
                 : "+f"(d[0]), "+f"(d[1]), "+f"(d[2]), "+f"(d[3])
                 : "r"(a[0]), "r"(a[1]), "r"(a[2]), "r"(a[3]), "r"(b0), "r"(b1));
}
static __device__ __forceinline__ uint32_t h2u(float x, float y) {
    __half2 h = __floats2half2_rn(x, y);
    return *(uint32_t*)&h;
}
static __device__ __forceinline__ void cp16(void* dst, const uint4* src) {
    unsigned a = (unsigned)__cvta_generic_to_shared(dst);
    asm volatile("cp.async.cg.shared.global [%0], [%1], 16;" :: "r"(a), "l"(src));
}

// x bits: lane[0:5) ktp[5:7) nt[7:10) t[10:15) h[15:20)
__global__ __launch_bounds__(256)
void prep_k(const float* __restrict__ kr, const float* __restrict__ ki) {
    int x = blockIdx.x * 256 + threadIdx.x;
    int lane = x & 31, ktp = (x >> 5) & 3, nt = (x >> 7) & 7;
    int t = (x >> 10) & 31, h = x >> 15;
    int g = lane >> 2, l = lane & 3;
    int row = ((h << 11) + (t << 6) + (nt << 3) + g) << 6;   // *64
    int k0 = (ktp << 4) + 2 * l, k1 = k0 + 8;
    gK[x] = make_uint4(h2u(kr[row + k0], kr[row + k0 + 1]),
                       h2u(kr[row + k1], kr[row + k1 + 1]),
                       h2u(ki[row + k0], ki[row + k0 + 1]),
                       h2u(ki[row + k1], ki[row + k1 + 1]));
}
__global__ __launch_bounds__(256)
void prep_v(const float* __restrict__ vr, const float* __restrict__ vi) {
    int x = blockIdx.x * 256 + threadIdx.x;
    int lane = x & 31, ktp = (x >> 5) & 3, nt = (x >> 7) & 7;
    int t = (x >> 10) & 31, h = x >> 15;
    int g = lane >> 2, l = lane & 3;
    int d = (nt << 3) + g;
    size_t base = ((size_t)h << 17) + d;                     // h*2048*64 + d
    int key0 = ((t << 6) + (ktp << 4) + 2 * l) << 6;         // *64
    int key8 = key0 + (8 << 6);
    float a0 = vr[base + key0], a1 = vr[base + key0 + 64];
    float a2 = vr[base + key8], a3 = vr[base + key8 + 64];
    float b0 = vi[base + key0], b1 = vi[base + key0 + 64];
    float b2 = vi[base + key8], b3 = vi[base + key8 + 64];
    gV[x]  = make_uint4(h2u(a0, a1), h2u(a2, a3), h2u(b0, b1), h2u(b2, b3));
    gVs[x] = make_uint2(h2u(a0 + b0, a1 + b1), h2u(a2 + b2, a3 + b3));
}

__global__ __launch_bounds__(128, 2)
void cvattn_mma(const float* __restrict__ qr_g, const float* __restrict__ qi_g,
                float* __restrict__ out)
{
    extern __shared__ uint4 smem4[];
    const int tid  = threadIdx.x;
    const int w    = tid >> 5;                 // 0..3
    const int lane = tid & 31;
    const int g    = lane >> 2;
    const int l    = lane & 3;
    const int bh   = blockIdx.y;
    const size_t hoff = (size_t)bh * (SLEN * 64);
    const int m0 = blockIdx.x << 6;            // 64-row query tile

    const uint4* srcK  = gK + ((size_t)bh << 15);   // 32 tiles x 1024
    const uint4* srcV  = gV + ((size_t)bh << 15);
    const uint4* srcVs = (const uint4*)gVs + ((size_t)bh << 14);   // 32 x 512

    // ---- Q fragments in fp16 (rows m0+w*16+g, +8), scaled ----
    uint32_t qa[4][4], qb[4][4];
    {
        const float* Q0r = qr_g + hoff + (size_t)(m0 + w * 16 + g) * 64;
        const float* Q1r = Q0r + 8 * 64;
        const float* Q0i = qi_g + hoff + (size_t)(m0 + w * 16 + g) * 64;
        const float* Q1i = Q0i + 8 * 64;
#pragma unroll
        for (int ktp = 0; ktp < 4; ++ktp) {
            int k0 = ktp * 16 + 2 * l, k1 = k0 + 8;
            qa[ktp][0] = h2u(Q0r[k0] * TEMP_INV, Q0r[k0 + 1] * TEMP_INV);
            qa[ktp][1] = h2u(Q1r[k0] * TEMP_INV, Q1r[k0 + 1] * TEMP_INV);
            qa[ktp][2] = h2u(Q0r[k1] * TEMP_INV, Q0r[k1 + 1] * TEMP_INV);
            qa[ktp][3] = h2u(Q1r[k1] * TEMP_INV, Q1r[k1 + 1] * TEMP_INV);
            qb[ktp][0] = h2u(Q0i[k0] * TEMP_INV, Q0i[k0 + 1] * TEMP_INV);
            qb[ktp][1] = h2u(Q1i[k0] * TEMP_INV, Q1i[k0 + 1] * TEMP_INV);
            qb[ktp][2] = h2u(Q0i[k1] * TEMP_INV, Q0i[k1 + 1] * TEMP_INV);
            qb[ktp][3] = h2u(Q1i[k1] * TEMP_INV, Q1i[k1 + 1] * TEMP_INV);
        }
    }

    // Karatsuba O accumulators
    float u1a[8][4], u2a[8][4], u3a[8][4];
#pragma unroll
    for (int nt = 0; nt < 8; ++nt)
#pragma unroll
        for (int j = 0; j < 4; ++j) { u1a[nt][j] = 0.f; u2a[nt][j] = 0.f; u3a[nt][j] = 0.f; }
    float lsum0 = 0.f, lsum1 = 0.f;

    // tile 0 load
#pragma unroll
    for (int j = 0; j < 8; ++j) {
        cp16(smem4 + tid + (j << 7),        srcK + tid + (j << 7));
        cp16(smem4 + 2048 + tid + (j << 7), srcV + tid + (j << 7));
    }
#pragma unroll
    for (int j = 0; j < 4; ++j)
        cp16(smem4 + 4096 + tid + (j << 7), srcVs + tid + (j << 7));
    asm volatile("cp.async.commit_group;" ::: "memory");
    asm volatile("cp.async.wait_group 0;" ::: "memory");
    __syncthreads();

    uint2* ppr = (uint2*)(smem4 + 5120 + w * 384);   // [kp 32][g 8]
    uint2* ppi = ppr + 256;
    uint2* pps = ppr + 512;

    for (int t = 0; t < NT; ++t) {
        if (t + 1 < NT) {
            const int nb = (t + 1) & 1;
            const int tb = (t + 1) << 10;
#pragma unroll
            for (int j = 0; j < 8; ++j) {
                cp16(smem4 + (nb << 10) + tid + (j << 7),        srcK + tb + tid + (j << 7));
                cp16(smem4 + 2048 + (nb << 10) + tid + (j << 7), srcV + tb + tid + (j << 7));
            }
#pragma unroll
            for (int j = 0; j < 4; ++j)
                cp16(smem4 + 4096 + (nb << 9) + tid + (j << 7),
                     srcVs + ((t + 1) << 9) + tid + (j << 7));
        }
        asm volatile("cp.async.commit_group;" ::: "memory");

        const uint4* kb = smem4 + ((t & 1) << 10);

        // ---- S = (Q/T) K^T (complex, direct 4-mult) ----
        float sre[8][4], sim_[8][4];
#pragma unroll
        for (int nt = 0; nt < 8; ++nt)
#pragma unroll
            for (int j = 0; j < 4; ++j) { sre[nt][j] = 0.f; sim_[nt][j] = 0.f; }

#pragma unroll
        for (int ktp = 0; ktp < 4; ++ktp) {
#pragma unroll
            for (int nt = 0; nt < 8; ++nt) {
                uint4 f = kb[(((nt << 2) + ktp) << 5) + lane];
                mma16(sre[nt],  qa[ktp], f.x, f.y);
                mma16(sim_[nt], qa[ktp], f.z, f.w);
                mma16(sre[nt],  qb[ktp], f.z ^ SGNH, f.w ^ SGNH);
                mma16(sim_[nt], qb[ktp], f.x, f.y);
            }
        }

        // ---- softmax on |S|; P (re, im, re+im) -> warp smem fp16 ----
#pragma unroll
        for (int nt = 0; nt < 8; ++nt) {
            float pr[4], pi[4];
#pragma unroll
            for (int j = 0; j < 4; ++j) {
                float x = sre[nt][j], y = sim_[nt][j];
                float r2 = fmaf(x, x, y * y);
                float ri = rsqrtf(fmaxf(r2, 1e-24f));
                float e  = __expf(r2 * ri);
                float wt = e * ri;
                pr[j] = x * wt;
                pi[j] = y * wt;
                if (j < 2) lsum0 += e; else lsum1 += e;
            }
            int idx = (((nt << 2) + l) << 3) + g;     // [kp][g]
            ppr[idx] = make_uint2(h2u(pr[0], pr[1]), h2u(pr[2], pr[3]));
            ppi[idx] = make_uint2(h2u(pi[0], pi[1]), h2u(pi[2], pi[3]));
            pps[idx] = make_uint2(h2u(pr[0] + pi[0], pr[1] + pi[1]),
                                  h2u(pr[2] + pi[2], pr[3] + pi[3]));
        }
        __syncwarp();

        // ---- O: u1 += Pr*Vr, u2 += Pi*Vi, u3 += Ps*Vs (3 MMAs/frag) ----
        const uint4* vb  = smem4 + 2048 + ((t & 1) << 10);
        const uint2* vsb = (const uint2*)(smem4 + 4096 + ((t & 1) << 9));
#pragma unroll
        for (int ktp = 0; ktp < 4; ++ktp) {
            int i0 = (((ktp << 3) + l) << 3) + g;      // kp = ktp*8+l
            int i1 = i0 + 32;                          // kp + 4
            uint2 r0 = ppr[i0], r1 = ppr[i1];
            uint2 q0 = ppi[i0], q1 = ppi[i1];
            uint2 s0 = pps[i0], s1 = pps[i1];
            uint32_t ap[4] = {r0.x, r0.y, r1.x, r1.y};
            uint32_t ai[4] = {q0.x, q0.y, q1.x, q1.y};
            uint32_t as[4] = {s0.x, s0.y, s1.x, s1.y};
#pragma unroll
            for (int nt = 0; nt < 8; ++nt) {
                uint4 v  = vb[(((nt << 2) + ktp) << 5) + lane];
                uint2 vs = vsb[(((nt << 2) + ktp) << 5) + lane];
                mma16(u1a[nt], ap, v.x, v.y);
                mma16(u2a[nt], ai, v.z, v.w);
                mma16(u3a[nt], as, vs.x, vs.y);
            }
        }

        asm volatile("cp.async.wait_group 0;" ::: "memory");
        __syncthreads();
    }

    // ---- epilogue: fold Karatsuba, normalize, store ----
    lsum0 += __shfl_xor_sync(0xffffffffu, lsum0, 1);
    lsum0 += __shfl_xor_sync(0xffffffffu, lsum0, 2);
    lsum1 += __shfl_xor_sync(0xffffffffu, lsum1, 1);
    lsum1 += __shfl_xor_sync(0xffffffffu, lsum1, 2);
    const float inv0 = 1.0f / lsum0;
    const float inv1 = 1.0f / lsum1;

    float* OutR = out + hoff;
    float* OutI = out + (size_t)PLANE + hoff;
    const int r0 = (m0 + w * 16 + g) * 64;
    const int r1 = r0 + 8 * 64;
#pragma unroll
    for (int nt = 0; nt < 8; ++nt) {
        int c = nt * 8 + 2 * l;
        float re0 = u1a[nt][0] - u2a[nt][0], re1 = u1a[nt][1] - u2a[nt][1];
        float re2 = u1a[nt][2] - u2a[nt][2], re3 = u1a[nt][3] - u2a[nt][3];
        float im0 = u3a[nt][0] - u1a[nt][0] - u2a[nt][0];
        float im1 = u3a[nt][1] - u1a[nt][1] - u2a[nt][1];
        float im2 = u3a[nt][2] - u1a[nt][2] - u2a[nt][2];
        float im3 = u3a[nt][3] - u1a[nt][3] - u2a[nt][3];
        *(float2*)(OutR + r0 + c) = make_float2(re0 * inv0, re1 * inv0);
        *(float2*)(OutI + r0 + c) = make_float2(im0 * inv0, im1 * inv0);
        *(float2*)(OutR + r1 + c) = make_float2(re2 * inv1, re3 * inv1);
        *(float2*)(OutI + r1 + c) = make_float2(im2 * inv1, im3 * inv1);
    }
}

extern "C" void kernel_launch(void* const* d_in, const int* in_sizes, int n_in,
                              void* d_out, int out_size)
{
    (void)in_sizes; (void)n_in; (void)out_size;
    prep_k<<<4096, 256>>>((const float*)d_in[2], (const float*)d_in[3]);
    prep_v<<<4096, 256>>>((const float*)d_in[4], (const float*)d_in[5]);

    cudaFuncSetAttribute(cvattn_mma, cudaFuncAttributeMaxDynamicSharedMemorySize, SMEM_BYTES);
    dim3 grid(SLEN / 64, 32);
    cvattn_mma<<<grid, 128, SMEM_BYTES>>>(
        (const float*)d_in[0], (const float*)d_in[1], (float*)d_out);
}

// round 13
// speedup vs baseline: 1.1914x; 1.1914x over previous
#include <cuda_runtime.h>
#include <cuda_fp16.h>
#include <cstdint>

// Complex attention via portable mma.sync m16n8k16 fp16 (f32 accum).
// Round 13: S C-fragment layout == P A-fragment layout (same lane), so P is
// repacked fp32->fp16 entirely in registers. P smem exchange deleted.
// 2 CTAs/SM (128 thr, 64 query rows each). Math identical to R11.
#define SLEN 2048
#define PLANE (4*8*2048*64)
#define TEMP_INV 0.125f
#define NT 32
#define SGNH 0x80008000u

// smem uint4 units: K[2][1024] @0, V[2][1024] @2048
#define SMEM_BYTES (4096*16)   // 65536

__device__ uint4 gK[32*32*1024];
__device__ uint4 gV[32*32*1024];

static __device__ __forceinline__ void mma16(float* d, const uint32_t* a,
                                             uint32_t b0, uint32_t b1) {
    asm volatile("mma.sync.aligned.m16n8k16.row.col.f32.f16.f16.f32 "
                 "{%0,%1,%2,%3},{%4,%5,%6,%7},{%8,%9},{%0,%1,%2,%3};"
                 : "+f"(d[0]), "+f"(d[1]), "+f"(d[2]), "+f"(d[3])
                 : "r"(a[0]), "r"(a[1]), "r"(a[2]), "r"(a[3]), "r"(b0), "r"(b1));
}
static __device__ __forceinline__ uint32_t h2u(float x, float y) {
    __half2 h = __floats2half2_rn(x, y);
    return *(uint32_t*)&h;
}
static __device__ __forceinline__ void cp16(void* dst, const uint4* src) {
    unsigned a = (unsigned)__cvta_generic_to_shared(dst);
    asm volatile("cp.async.cg.shared.global [%0], [%1], 16;" :: "r"(a), "l"(src));
}

// x bits: lane[0:5) ktp[5:7) nt[7:10) t[10:15) h[15:20)
__global__ __launch_bounds__(256)
void prep_k(const float* __restrict__ kr, const float* __restrict__ ki) {
    int x = blockIdx.x * 256 + threadIdx.x;
    int lane = x & 31, ktp = (x >> 5) & 3, nt = (x >> 7) & 7;
    int t = (x >> 10) & 31, h = x >> 15;
    int g = lane >> 2, l = lane & 3;
    int row = ((h << 11) + (t << 6) + (nt << 3) + g) << 6;   // *64
    int k0 = (ktp << 4) + 2 * l, k1 = k0 + 8;
    gK[x] = make_uint4(h2u(kr[row + k0], kr[row + k0 + 1]),
                       h2u(kr[row + k1], kr[row + k1 + 1]),
                       h2u(ki[row + k0], ki[row + k0 + 1]),
                       h2u(ki[row + k1], ki[row + k1 + 1]));
}
__global__ __launch_bounds__(256)
void prep_v(const float* __restrict__ vr, const float* __restrict__ vi) {
    int x = blockIdx.x * 256 + threadIdx.x;
    int lane = x & 31, ktp = (x >> 5) & 3, nt = (x >> 7) & 7;
    int t = (x >> 10) & 31, h = x >> 15;
    int g = lane >> 2, l = lane & 3;
    int d = (nt << 3) + g;
    size_t base = ((size_t)h << 17) + d;                     // h*2048*64 + d
    int key0 = ((t << 6) + (ktp << 4) + 2 * l) << 6;         // *64
    int key8 = key0 + (8 << 6);
    gV[x] = make_uint4(h2u(vr[base + key0], vr[base + key0 + 64]),
                       h2u(vr[base + key8], vr[base + key8 + 64]),
                       h2u(vi[base + key0], vi[base + key0 + 64]),
                       h2u(vi[base + key8], vi[base + key8 + 64]));
}

__global__ __launch_bounds__(128, 2)
void cvattn_mma(const float* __restrict__ qr_g, const float* __restrict__ qi_g,
                float* __restrict__ out)
{
    extern __shared__ uint4 smem4[];
    const int tid  = threadIdx.x;
    const int w    = tid >> 5;                 // 0..3
    const int lane = tid & 31;
    const int g    = lane >> 2;
    const int l    = lane & 3;
    const int bh   = blockIdx.y;
    const size_t hoff = (size_t)bh * (SLEN * 64);
    const int m0 = blockIdx.x << 6;            // 64-row query tile

    const uint4* srcK = gK + ((size_t)bh << 15);   // 32 tiles x 1024
    const uint4* srcV = gV + ((size_t)bh << 15);

    // ---- Q fragments in fp16 (rows m0+w*16+g, +8), scaled ----
    uint32_t qa[4][4], qb[4][4];
    {
        const float* Q0r = qr_g + hoff + (size_t)(m0 + w * 16 + g) * 64;
        const float* Q1r = Q0r + 8 * 64;
        const float* Q0i = qi_g + hoff + (size_t)(m0 + w * 16 + g) * 64;
        const float* Q1i = Q0i + 8 * 64;
#pragma unroll
        for (int ktp = 0; ktp < 4; ++ktp) {
            int k0 = ktp * 16 + 2 * l, k1 = k0 + 8;
            qa[ktp][0] = h2u(Q0r[k0] * TEMP_INV, Q0r[k0 + 1] * TEMP_INV);
            qa[ktp][1] = h2u(Q1r[k0] * TEMP_INV, Q1r[k0 + 1] * TEMP_INV);
            qa[ktp][2] = h2u(Q0r[k1] * TEMP_INV, Q0r[k1 + 1] * TEMP_INV);
            qa[ktp][3] = h2u(Q1r[k1] * TEMP_INV, Q1r[k1 + 1] * TEMP_INV);
            qb[ktp][0] = h2u(Q0i[k0] * TEMP_INV, Q0i[k0 + 1] * TEMP_INV);
            qb[ktp][1] = h2u(Q1i[k0] * TEMP_INV, Q1i[k0 + 1] * TEMP_INV);
            qb[ktp][2] = h2u(Q0i[k1] * TEMP_INV, Q0i[k1 + 1] * TEMP_INV);
            qb[ktp][3] = h2u(Q1i[k1] * TEMP_INV, Q1i[k1 + 1] * TEMP_INV);
        }
    }

    float ore[8][4], oim[8][4];
#pragma unroll
    for (int nt = 0; nt < 8; ++nt)
#pragma unroll
        for (int j = 0; j < 4; ++j) { ore[nt][j] = 0.f; oim[nt][j] = 0.f; }
    float lsum0 = 0.f, lsum1 = 0.f;

    // tile 0 load: K 1024 + V 1024 chunks with 128 threads
#pragma unroll
    for (int j = 0; j < 8; ++j) {
        cp16(smem4 + tid + (j << 7),        srcK + tid + (j << 7));
        cp16(smem4 + 2048 + tid + (j << 7), srcV + tid + (j << 7));
    }
    asm volatile("cp.async.commit_group;" ::: "memory");
    asm volatile("cp.async.wait_group 0;" ::: "memory");
    __syncthreads();

    for (int t = 0; t < NT; ++t) {
        if (t + 1 < NT) {
            const int nb = (t + 1) & 1, tb = (t + 1) << 10;
#pragma unroll
            for (int j = 0; j < 8; ++j) {
                cp16(smem4 + (nb << 10) + tid + (j << 7),        srcK + tb + tid + (j << 7));
                cp16(smem4 + 2048 + (nb << 10) + tid + (j << 7), srcV + tb + tid + (j << 7));
            }
        }
        asm volatile("cp.async.commit_group;" ::: "memory");

        const uint4* kb = smem4 + ((t & 1) << 10);

        // ---- S = (Q/T) K^T (complex) ----
        float sre[8][4], sim_[8][4];
#pragma unroll
        for (int nt = 0; nt < 8; ++nt)
#pragma unroll
            for (int j = 0; j < 4; ++j) { sre[nt][j] = 0.f; sim_[nt][j] = 0.f; }

#pragma unroll
        for (int ktp = 0; ktp < 4; ++ktp) {
#pragma unroll
            for (int nt = 0; nt < 8; ++nt) {
                uint4 f = kb[(((nt << 2) + ktp) << 5) + lane];
                mma16(sre[nt],  qa[ktp], f.x, f.y);
                mma16(sim_[nt], qa[ktp], f.z, f.w);
                mma16(sre[nt],  qb[ktp], f.z ^ SGNH, f.w ^ SGNH);
                mma16(sim_[nt], qb[ktp], f.x, f.y);
            }
        }

        // ---- softmax on |S|; pack P as fp16 A-fragments IN REGISTERS ----
        // C-frag (j0..j3) == A-frag pair layout for the same lane: no exchange.
        uint32_t prh[8][2], pih[8][2];
#pragma unroll
        for (int nt = 0; nt < 8; ++nt) {
            float pr[4], pi[4];
#pragma unroll
            for (int j = 0; j < 4; ++j) {
                float x = sre[nt][j], y = sim_[nt][j];
                float r2 = fmaf(x, x, y * y);
                float ri = rsqrtf(fmaxf(r2, 1e-24f));
                float e  = __expf(r2 * ri);
                float wt = e * ri;
                pr[j] = x * wt;
                pi[j] = y * wt;
                if (j < 2) lsum0 += e; else lsum1 += e;
            }
            prh[nt][0] = h2u(pr[0], pr[1]);
            prh[nt][1] = h2u(pr[2], pr[3]);
            pih[nt][0] = h2u(pi[0], pi[1]);
            pih[nt][1] = h2u(pi[2], pi[3]);
        }

        // ---- O += P V (complex), A-frags straight from registers ----
        const uint4* vb = smem4 + 2048 + ((t & 1) << 10);
#pragma unroll
        for (int ktp = 0; ktp < 4; ++ktp) {
            uint32_t ap[4]  = {prh[2*ktp][0], prh[2*ktp][1], prh[2*ktp+1][0], prh[2*ktp+1][1]};
            uint32_t ai[4]  = {pih[2*ktp][0], pih[2*ktp][1], pih[2*ktp+1][0], pih[2*ktp+1][1]};
            uint32_t ain[4] = {ai[0] ^ SGNH, ai[1] ^ SGNH, ai[2] ^ SGNH, ai[3] ^ SGNH};
#pragma unroll
            for (int nt = 0; nt < 8; ++nt) {
                uint4 v = vb[(((nt << 2) + ktp) << 5) + lane];
                mma16(ore[nt], ap,  v.x, v.y);
                mma16(oim[nt], ap,  v.z, v.w);
                mma16(ore[nt], ain, v.z, v.w);
                mma16(oim[nt], ai,  v.x, v.y);
            }
        }

        asm volatile("cp.async.wait_group 0;" ::: "memory");
        __syncthreads();
    }

    // ---- epilogue ----
    lsum0 += __shfl_xor_sync(0xffffffffu, lsum0, 1);
    lsum0 += __shfl_xor_sync(0xffffffffu, lsum0, 2);
    lsum1 += __shfl_xor_sync(0xffffffffu, lsum1, 1);
    lsum1 += __shfl_xor_sync(0xffffffffu, lsum1, 2);
    const float inv0 = 1.0f / lsum0;
    const float inv1 = 1.0f / lsum1;

    float* OutR = out + hoff;
    float* OutI = out + (size_t)PLANE + hoff;
    const int r0 = (m0 + w * 16 + g) * 64;
    const int r1 = r0 + 8 * 64;
#pragma unroll
    for (int nt = 0; nt < 8; ++nt) {
        int c = nt * 8 + 2 * l;
        *(float2*)(OutR + r0 + c) = make_float2(ore[nt][0] * inv0, ore[nt][1] * inv0);
        *(float2*)(OutI + r0 + c) = make_float2(oim[nt][0] * inv0, oim[nt][1] * inv0);
        *(float2*)(OutR + r1 + c) = make_float2(ore[nt][2] * inv1, ore[nt][3] * inv1);
        *(float2*)(OutI + r1 + c) = make_float2(oim[nt][2] * inv1, oim[nt][3] * inv1);
    }
}

extern "C" void kernel_launch(void* const* d_in, const int* in_sizes, int n_in,
                              void* d_out, int out_size)
{
    (void)in_sizes; (void)n_in; (void)out_size;
    prep_k<<<4096, 256>>>((const float*)d_in[2], (const float*)d_in[3]);
    prep_v<<<4096, 256>>>((const float*)d_in[4], (const float*)d_in[5]);

    cudaFuncSetAttribute(cvattn_mma, cudaFuncAttributeMaxDynamicSharedMemorySize, SMEM_BYTES);
    dim3 grid(SLEN / 64, 32);
    cvattn_mma<<<grid, 128, SMEM_BYTES>>>(
        (const float*)d_in[0], (const float*)d_in[1], (float*)d_out);
}

// round 14
// speedup vs baseline: 1.1964x; 1.0042x over previous
#include <cuda_runtime.h>
#include <cuda_fp16.h>
#include <cstdint>

// Complex attention via portable mma.sync m16n8k16 fp16 (f32 accum).
// Round 14: Karatsuba 3-mult on QK stage (transient accumulators):
//   u1=Qr*Kr, u2=Qi*Ki, u3=(Qr+Qi)*(Kr+Ki); S_re=u1-u2, S_im=u3-u1-u2.
// Ks baked in prepass; Qs in registers. P stays register-resident (R13).
#define SLEN 2048
#define PLANE (4*8*2048*64)
#define TEMP_INV 0.125f
#define NT 32
#define SGNH 0x80008000u

// smem uint4 units: K[2][1024] @0, Ks[2][512] @2048, V[2][1024] @3072
#define SMEM_BYTES (5120*16)   // 81920

__device__ uint4 gK[32*32*1024];
__device__ uint2 gKs[32*32*1024];
__device__ uint4 gV[32*32*1024];

static __device__ __forceinline__ void mma16(float* d, const uint32_t* a,
                                             uint32_t b0, uint32_t b1) {
    asm volatile("mma.sync.aligned.m16n8k16.row.col.f32.f16.f16.f32 "
                 "{%0,%1,%2,%3},{%4,%5,%6,%7},{%8,%9},{%0,%1,%2,%3};"
                 : "+f"(d[0]), "+f"(d[1]), "+f"(d[2]), "+f"(d[3])
                 : "r"(a[0]), "r"(a[1]), "r"(a[2]), "r"(a[3]), "r"(b0), "r"(b1));
}
static __device__ __forceinline__ uint32_t h2u(float x, float y) {
    __half2 h = __floats2half2_rn(x, y);
    return *(uint32_t*)&h;
}
static __device__ __forceinline__ void cp16(void* dst, const uint4* src) {
    unsigned a = (unsigned)__cvta_generic_to_shared(dst);
    asm volatile("cp.async.cg.shared.global [%0], [%1], 16;" :: "r"(a), "l"(src));
}

// x bits: lane[0:5) ktp[5:7) nt[7:10) t[10:15) h[15:20)
__global__ __launch_bounds__(256)
void prep_k(const float* __restrict__ kr, const float* __restrict__ ki) {
    int x = blockIdx.x * 256 + threadIdx.x;
    int lane = x & 31, ktp = (x >> 5) & 3, nt = (x >> 7) & 7;
    int t = (x >> 10) & 31, h = x >> 15;
    int g = lane >> 2, l = lane & 3;
    int row = ((h << 11) + (t << 6) + (nt << 3) + g) << 6;   // *64
    int k0 = (ktp << 4) + 2 * l, k1 = k0 + 8;
    float r0 = kr[row + k0], r1 = kr[row + k0 + 1];
    float r2 = kr[row + k1], r3 = kr[row + k1 + 1];
    float i0 = ki[row + k0], i1 = ki[row + k0 + 1];
    float i2 = ki[row + k1], i3 = ki[row + k1 + 1];
    gK[x]  = make_uint4(h2u(r0, r1), h2u(r2, r3), h2u(i0, i1), h2u(i2, i3));
    gKs[x] = make_uint2(h2u(r0 + i0, r1 + i1), h2u(r2 + i2, r3 + i3));
}
__global__ __launch_bounds__(256)
void prep_v(const float* __restrict__ vr, const float* __restrict__ vi) {
    int x = blockIdx.x * 256 + threadIdx.x;
    int lane = x & 31, ktp = (x >> 5) & 3, nt = (x >> 7) & 7;
    int t = (x >> 10) & 31, h = x >> 15;
    int g = lane >> 2, l = lane & 3;
    int d = (nt << 3) + g;
    size_t base = ((size_t)h << 17) + d;                     // h*2048*64 + d
    int key0 = ((t << 6) + (ktp << 4) + 2 * l) << 6;         // *64
    int key8 = key0 + (8 << 6);
    gV[x] = make_uint4(h2u(vr[base + key0], vr[base + key0 + 64]),
                       h2u(vr[base + key8], vr[base + key8 + 64]),
                       h2u(vi[base + key0], vi[base + key0 + 64]),
                       h2u(vi[base + key8], vi[base + key8 + 64]));
}

__global__ __launch_bounds__(128, 2)
void cvattn_mma(const float* __restrict__ qr_g, const float* __restrict__ qi_g,
                float* __restrict__ out)
{
    extern __shared__ uint4 smem4[];
    const int tid  = threadIdx.x;
    const int w    = tid >> 5;                 // 0..3
    const int lane = tid & 31;
    const int g    = lane >> 2;
    const int l    = lane & 3;
    const int bh   = blockIdx.y;
    const size_t hoff = (size_t)bh * (SLEN * 64);
    const int m0 = blockIdx.x << 6;            // 64-row query tile

    const uint4* srcK  = gK + ((size_t)bh << 15);              // 32 x 1024
    const uint4* srcKs = (const uint4*)gKs + ((size_t)bh << 14); // 32 x 512
    const uint4* srcV  = gV + ((size_t)bh << 15);

    // ---- Q fragments fp16 (rows m0+w*16+g, +8), scaled; Qs = Qr+Qi ----
    uint32_t qa[4][4], qb[4][4], qs[4][4];
    {
        const float* Q0r = qr_g + hoff + (size_t)(m0 + w * 16 + g) * 64;
        const float* Q1r = Q0r + 8 * 64;
        const float* Q0i = qi_g + hoff + (size_t)(m0 + w * 16 + g) * 64;
        const float* Q1i = Q0i + 8 * 64;
#pragma unroll
        for (int ktp = 0; ktp < 4; ++ktp) {
            int k0 = ktp * 16 + 2 * l, k1 = k0 + 8;
            float a0 = Q0r[k0] * TEMP_INV, a1 = Q0r[k0 + 1] * TEMP_INV;
            float a2 = Q1r[k0] * TEMP_INV, a3 = Q1r[k0 + 1] * TEMP_INV;
            float a4 = Q0r[k1] * TEMP_INV, a5 = Q0r[k1 + 1] * TEMP_INV;
            float a6 = Q1r[k1] * TEMP_INV, a7 = Q1r[k1 + 1] * TEMP_INV;
            float b0 = Q0i[k0] * TEMP_INV, b1 = Q0i[k0 + 1] * TEMP_INV;
            float b2 = Q1i[k0] * TEMP_INV, b3 = Q1i[k0 + 1] * TEMP_INV;
            float b4 = Q0i[k1] * TEMP_INV, b5 = Q0i[k1 + 1] * TEMP_INV;
            float b6 = Q1i[k1] * TEMP_INV, b7 = Q1i[k1 + 1] * TEMP_INV;
            qa[ktp][0] = h2u(a0, a1); qa[ktp][1] = h2u(a2, a3);
            qa[ktp][2] = h2u(a4, a5); qa[ktp][3] = h2u(a6, a7);
            qb[ktp][0] = h2u(b0, b1); qb[ktp][1] = h2u(b2, b3);
            qb[ktp][2] = h2u(b4, b5); qb[ktp][3] = h2u(b6, b7);
            qs[ktp][0] = h2u(a0 + b0, a1 + b1); qs[ktp][1] = h2u(a2 + b2, a3 + b3);
            qs[ktp][2] = h2u(a4 + b4, a5 + b5); qs[ktp][3] = h2u(a6 + b6, a7 + b7);
        }
    }

    float ore[8][4], oim[8][4];
#pragma unroll
    for (int nt = 0; nt < 8; ++nt)
#pragma unroll
        for (int j = 0; j < 4; ++j) { ore[nt][j] = 0.f; oim[nt][j] = 0.f; }
    float lsum0 = 0.f, lsum1 = 0.f;

    // tile 0 load: K 1024 + Ks 512 + V 1024 uint4 chunks, 128 threads
#pragma unroll
    for (int j = 0; j < 8; ++j) {
        cp16(smem4 + tid + (j << 7),        srcK + tid + (j << 7));
        cp16(smem4 + 3072 + tid + (j << 7), srcV + tid + (j << 7));
    }
#pragma unroll
    for (int j = 0; j < 4; ++j)
        cp16(smem4 + 2048 + tid + (j << 7), srcKs + tid + (j << 7));
    asm volatile("cp.async.commit_group;" ::: "memory");
    asm volatile("cp.async.wait_group 0;" ::: "memory");
    __syncthreads();

    for (int t = 0; t < NT; ++t) {
        if (t + 1 < NT) {
            const int nb = (t + 1) & 1, tb = (t + 1) << 10;
#pragma unroll
            for (int j = 0; j < 8; ++j) {
                cp16(smem4 + (nb << 10) + tid + (j << 7),        srcK + tb + tid + (j << 7));
                cp16(smem4 + 3072 + (nb << 10) + tid + (j << 7), srcV + tb + tid + (j << 7));
            }
#pragma unroll
            for (int j = 0; j < 4; ++j)
                cp16(smem4 + 2048 + (nb << 9) + tid + (j << 7),
                     srcKs + ((t + 1) << 9) + tid + (j << 7));
        }
        asm volatile("cp.async.commit_group;" ::: "memory");

        const uint4* kb  = smem4 + ((t & 1) << 10);
        const uint2* ksb = (const uint2*)(smem4 + 2048 + ((t & 1) << 9));

        // ---- QK Karatsuba: u1=Qr*Kr, u2=Qi*Ki, u3=Qs*Ks ----
        float u1[8][4], u2[8][4], u3[8][4];
#pragma unroll
        for (int nt = 0; nt < 8; ++nt)
#pragma unroll
            for (int j = 0; j < 4; ++j) { u1[nt][j] = 0.f; u2[nt][j] = 0.f; u3[nt][j] = 0.f; }

#pragma unroll
        for (int ktp = 0; ktp < 4; ++ktp) {
#pragma unroll
            for (int nt = 0; nt < 8; ++nt) {
                int fi = (((nt << 2) + ktp) << 5) + lane;
                uint4 f  = kb[fi];
                uint2 fs = ksb[fi];
                mma16(u1[nt], qa[ktp], f.x, f.y);
                mma16(u2[nt], qb[ktp], f.z, f.w);
                mma16(u3[nt], qs[ktp], fs.x, fs.y);
            }
        }

        // ---- fold + softmax on |S|; P packed to fp16 A-frags in registers ----
        uint32_t prh[8][2], pih[8][2];
#pragma unroll
        for (int nt = 0; nt < 8; ++nt) {
            float pr[4], pi[4];
#pragma unroll
            for (int j = 0; j < 4; ++j) {
                float x = u1[nt][j] - u2[nt][j];
                float y = u3[nt][j] - u1[nt][j] - u2[nt][j];
                float r2 = fmaf(x, x, y * y);
                float ri = rsqrtf(fmaxf(r2, 1e-24f));
                float e  = __expf(r2 * ri);
                float wt = e * ri;
                pr[j] = x * wt;
                pi[j] = y * wt;
                if (j < 2) lsum0 += e; else lsum1 += e;
            }
            prh[nt][0] = h2u(pr[0], pr[1]);
            prh[nt][1] = h2u(pr[2], pr[3]);
            pih[nt][0] = h2u(pi[0], pi[1]);
            pih[nt][1] = h2u(pi[2], pi[3]);
        }

        // ---- O += P V (complex), A-frags straight from registers ----
        const uint4* vb = smem4 + 3072 + ((t & 1) << 10);
#pragma unroll
        for (int ktp = 0; ktp < 4; ++ktp) {
            uint32_t ap[4]  = {prh[2*ktp][0], prh[2*ktp][1], prh[2*ktp+1][0], prh[2*ktp+1][1]};
            uint32_t ai[4]  = {pih[2*ktp][0], pih[2*ktp][1], pih[2*ktp+1][0], pih[2*ktp+1][1]};
            uint32_t ain[4] = {ai[0] ^ SGNH, ai[1] ^ SGNH, ai[2] ^ SGNH, ai[3] ^ SGNH};
#pragma unroll
            for (int nt = 0; nt < 8; ++nt) {
                uint4 v = vb[(((nt << 2) + ktp) << 5) + lane];
                mma16(ore[nt], ap,  v.x, v.y);
                mma16(oim[nt], ap,  v.z, v.w);
                mma16(ore[nt], ain, v.z, v.w);
                mma16(oim[nt], ai,  v.x, v.y);
            }
        }

        asm volatile("cp.async.wait_group 0;" ::: "memory");
        __syncthreads();
    }

    // ---- epilogue ----
    lsum0 += __shfl_xor_sync(0xffffffffu, lsum0, 1);
    lsum0 += __shfl_xor_sync(0xffffffffu, lsum0, 2);
    lsum1 += __shfl_xor_sync(0xffffffffu, lsum1, 1);
    lsum1 += __shfl_xor_sync(0xffffffffu, lsum1, 2);
    const float inv0 = 1.0f / lsum0;
    const float inv1 = 1.0f / lsum1;

    float* OutR = out + hoff;
    float* OutI = out + (size_t)PLANE + hoff;
    const int r0 = (m0 + w * 16 + g) * 64;
    const int r1 = r0 + 8 * 64;
#pragma unroll
    for (int nt = 0; nt < 8; ++nt) {
        int c = nt * 8 + 2 * l;
        *(float2*)(OutR + r0 + c) = make_float2(ore[nt][0] * inv0, ore[nt][1] * inv0);
        *(float2*)(OutI + r0 + c) = make_float2(oim[nt][0] * inv0, oim[nt][1] * inv0);
        *(float2*)(OutR + r1 + c) = make_float2(ore[nt][2] * inv1, ore[nt][3] * inv1);
        *(float2*)(OutI + r1 + c) = make_float2(oim[nt][2] * inv1, oim[nt][3] * inv1);
    }
}

extern "C" void kernel_launch(void* const* d_in, const int* in_sizes, int n_in,
                              void* d_out, int out_size)
{
    (void)in_sizes; (void)n_in; (void)out_size;
    prep_k<<<4096, 256>>>((const float*)d_in[2], (const float*)d_in[3]);
    prep_v<<<4096, 256>>>((const float*)d_in[4], (const float*)d_in[5]);

    cudaFuncSetAttribute(cvattn_mma, cudaFuncAttributeMaxDynamicSharedMemorySize, SMEM_BYTES);
    dim3 grid(SLEN / 64, 32);
    cvattn_mma<<<grid, 128, SMEM_BYTES>>>(
        (const float*)d_in[0], (const float*)d_in[1], (float*)d_out);
}